// round 10
// baseline (speedup 1.0000x reference)
#include <cuda_runtime.h>

// LIF SNN scan: T=1024 timesteps, B*N = 65536 independent columns.
// out layout: [ spikes (T*BN) | v_final (BN) | i_final (BN) ]
// R10: rolling prefetch ring (constant 32 LDGs in flight) with float4
// (4 columns/thread): LDG.128/STG.128 -> 512B warp bursts, LSU ops per byte
// halved again vs R9. block=32, grid=512 (3.46 CTA/SM; skew proven immaterial).

#define T_STEPS 1024
#define BN      65536
#define NCOL4   (BN / 4)    // float4 columns = 16384
#define PF      32

__global__ __launch_bounds__(32, 4)
void snn_lif_kernel(const float4* __restrict__ x, float4* __restrict__ out) {
    const int idx = blockIdx.x * blockDim.x + threadIdx.x;  // float4-column id
    const float4* xp = x + idx;
    float4*       zp = out + idx;

    float v0 = 0.0f, v1 = 0.0f, v2 = 0.0f, v3 = 0.0f;   // membrane potentials
    float c0 = 0.0f, c1 = 0.0f, c2 = 0.0f, c3 = 0.0f;   // synaptic currents

    // prologue: fill the prefetch ring (32 independent LDG.128 in flight)
    float4 xbuf[PF];
    #pragma unroll
    for (int j = 0; j < PF; ++j)
        xbuf[j] = __ldg(xp + (long)j * NCOL4);

    // dt*tau_mem_inv = 0.1, (1 - dt*tau_syn_inv) = 0.8, v_th = 1, v_reset = 0
    for (int t0 = 0; t0 < T_STEPS - PF; t0 += PF) {
        #pragma unroll
        for (int j = 0; j < PF; ++j) {
            const float4 xt = xbuf[j];
            // immediately re-issue this slot for t0+PF+j (ring stays full)
            xbuf[j] = __ldg(xp + (long)(t0 + PF + j) * NCOL4);

            float4 z;

            const float vd0 = fmaf(0.1f, c0 - v0, v0);
            const bool  f0  = (vd0 > 1.0f);
            z.x = f0 ? 1.0f : 0.0f;  v0 = f0 ? 0.0f : vd0;  c0 = fmaf(c0, 0.8f, xt.x);

            const float vd1 = fmaf(0.1f, c1 - v1, v1);
            const bool  f1  = (vd1 > 1.0f);
            z.y = f1 ? 1.0f : 0.0f;  v1 = f1 ? 0.0f : vd1;  c1 = fmaf(c1, 0.8f, xt.y);

            const float vd2 = fmaf(0.1f, c2 - v2, v2);
            const bool  f2  = (vd2 > 1.0f);
            z.z = f2 ? 1.0f : 0.0f;  v2 = f2 ? 0.0f : vd2;  c2 = fmaf(c2, 0.8f, xt.z);

            const float vd3 = fmaf(0.1f, c3 - v3, v3);
            const bool  f3  = (vd3 > 1.0f);
            z.w = f3 ? 1.0f : 0.0f;  v3 = f3 ? 0.0f : vd3;  c3 = fmaf(c3, 0.8f, xt.w);

            zp[(long)(t0 + j) * NCOL4] = z;
        }
    }

    // epilogue: last PF steps, no prefetch
    #pragma unroll
    for (int j = 0; j < PF; ++j) {
        const float4 xt = xbuf[j];

        float4 z;

        const float vd0 = fmaf(0.1f, c0 - v0, v0);
        const bool  f0  = (vd0 > 1.0f);
        z.x = f0 ? 1.0f : 0.0f;  v0 = f0 ? 0.0f : vd0;  c0 = fmaf(c0, 0.8f, xt.x);

        const float vd1 = fmaf(0.1f, c1 - v1, v1);
        const bool  f1  = (vd1 > 1.0f);
        z.y = f1 ? 1.0f : 0.0f;  v1 = f1 ? 0.0f : vd1;  c1 = fmaf(c1, 0.8f, xt.y);

        const float vd2 = fmaf(0.1f, c2 - v2, v2);
        const bool  f2  = (vd2 > 1.0f);
        z.z = f2 ? 1.0f : 0.0f;  v2 = f2 ? 0.0f : vd2;  c2 = fmaf(c2, 0.8f, xt.z);

        const float vd3 = fmaf(0.1f, c3 - v3, v3);
        const bool  f3  = (vd3 > 1.0f);
        z.w = f3 ? 1.0f : 0.0f;  v3 = f3 ? 0.0f : vd3;  c3 = fmaf(c3, 0.8f, xt.w);

        zp[(long)(T_STEPS - PF + j) * NCOL4] = z;
    }

    // final state after the full scan: v then i, each BN floats (NCOL4 float4)
    float4 vf; vf.x = v0; vf.y = v1; vf.z = v2; vf.w = v3;
    float4 cf; cf.x = c0; cf.y = c1; cf.z = c2; cf.w = c3;
    out[(long)T_STEPS * NCOL4 + idx]          = vf;
    out[(long)T_STEPS * NCOL4 + NCOL4 + idx]  = cf;
}

extern "C" void kernel_launch(void* const* d_in, const int* in_sizes, int n_in,
                              void* d_out, int out_size) {
    const float4* x   = (const float4*)d_in[0];
    float4*       out = (float4*)d_out;
    (void)in_sizes; (void)n_in; (void)out_size;

    snn_lif_kernel<<<NCOL4 / 32, 32>>>(x, out);
}

// round 11
// speedup vs baseline: 1.0067x; 1.0067x over previous
#include <cuda_runtime.h>

// LIF SNN scan: T=1024 timesteps, B*N = 65536 independent columns.
// out layout: [ spikes (T*BN) | v_final (BN) | i_final (BN) ]
// R11: R9 body (float2, rolling PF=32 ring — best: 76.2us kernel, 80.3% DRAM)
// with stores marked streaming (__stcs): the 256MB spike stream is never
// re-read, evict-first keeps L2 for the read stream. Loads stay __ldg —
// R2 proved __ldcs breaks ptxas load batching; the explicit ring + __ldg
// pins 32 LDG.64 in flight regardless.

#define T_STEPS 1024
#define BN      65536
#define NCOL2   (BN / 2)    // float2 columns
#define PF      32

__global__ __launch_bounds__(64, 4)
void snn_lif_kernel(const float2* __restrict__ x, float2* __restrict__ out) {
    const int idx = blockIdx.x * blockDim.x + threadIdx.x;  // float2-column id
    const float2* xp = x + idx;
    float2*       zp = out + idx;

    float v0 = 0.0f, v1 = 0.0f;     // membrane potentials
    float c0 = 0.0f, c1 = 0.0f;     // synaptic currents

    // prologue: fill the prefetch ring (32 independent LDG.64 in flight)
    float2 xbuf[PF];
    #pragma unroll
    for (int j = 0; j < PF; ++j)
        xbuf[j] = __ldg(xp + (long)j * NCOL2);

    // dt*tau_mem_inv = 0.1, (1 - dt*tau_syn_inv) = 0.8, v_th = 1, v_reset = 0
    for (int t0 = 0; t0 < T_STEPS - PF; t0 += PF) {
        #pragma unroll
        for (int j = 0; j < PF; ++j) {
            const float2 xt = xbuf[j];
            // immediately re-issue this slot for t0+PF+j (ring stays full)
            xbuf[j] = __ldg(xp + (long)(t0 + PF + j) * NCOL2);

            float2 z;

            const float vd0 = fmaf(0.1f, c0 - v0, v0);
            const bool  f0  = (vd0 > 1.0f);
            z.x = f0 ? 1.0f : 0.0f;
            v0  = f0 ? 0.0f : vd0;
            c0  = fmaf(c0, 0.8f, xt.x);

            const float vd1 = fmaf(0.1f, c1 - v1, v1);
            const bool  f1  = (vd1 > 1.0f);
            z.y = f1 ? 1.0f : 0.0f;
            v1  = f1 ? 0.0f : vd1;
            c1  = fmaf(c1, 0.8f, xt.y);

            __stcs(zp + (long)(t0 + j) * NCOL2, z);
        }
    }

    // epilogue: last PF steps, no prefetch
    #pragma unroll
    for (int j = 0; j < PF; ++j) {
        const float2 xt = xbuf[j];

        float2 z;

        const float vd0 = fmaf(0.1f, c0 - v0, v0);
        const bool  f0  = (vd0 > 1.0f);
        z.x = f0 ? 1.0f : 0.0f;
        v0  = f0 ? 0.0f : vd0;
        c0  = fmaf(c0, 0.8f, xt.x);

        const float vd1 = fmaf(0.1f, c1 - v1, v1);
        const bool  f1  = (vd1 > 1.0f);
        z.y = f1 ? 1.0f : 0.0f;
        v1  = f1 ? 0.0f : vd1;
        c1  = fmaf(c1, 0.8f, xt.y);

        __stcs(zp + (long)(T_STEPS - PF + j) * NCOL2, z);
    }

    // final state after the full scan: v then i, each BN floats (NCOL2 float2)
    float2 vf; vf.x = v0; vf.y = v1;
    float2 cf; cf.x = c0; cf.y = c1;
    __stcs(out + (long)T_STEPS * NCOL2 + idx,         vf);
    __stcs(out + (long)T_STEPS * NCOL2 + NCOL2 + idx, cf);
}

extern "C" void kernel_launch(void* const* d_in, const int* in_sizes, int n_in,
                              void* d_out, int out_size) {
    const float2* x   = (const float2*)d_in[0];
    float2*       out = (float2*)d_out;
    (void)in_sizes; (void)n_in; (void)out_size;

    snn_lif_kernel<<<NCOL2 / 64, 64>>>(x, out);
}